// round 6
// baseline (speedup 1.0000x reference)
#include <cuda_runtime.h>
#include <stdint.h>

#define IN_F   4096
#define OUT_F  4096
#define RANK_  16
#define MROWS  16384            // 4*4096 flattened rows
#define TH_    0xE6666600u      // bits < TH_  <=>  uniform(bits) < 0.9f (exact)
#define KC     128              // k-chunk (k1)
#define BM1    16               // rows per block (k1)
#define RB     16               // rows per block (k2)
#define CBT    512              // col-chunk (k2)

typedef unsigned long long u64;

// scratch (allocation-free rule: __device__ globals)
static __device__ float g_At[IN_F * RANK_];   // [k][r]  = A[r][k]
static __device__ float g_Bt[RANK_ * OUT_F];  // [r][o]  = B[o][r] * (scaling/keep)
static __device__ u64   g_T2[MROWS * RANK_];  // T packed as (v,v) f32x2
// opaque rotate multipliers (prevents ptxas strength-reduction to SHF)
static __device__ unsigned g_mul[4] = {1u << 26, 1u << 6, 1u << 16, 1u << 24};

// ---------- f32x2 helpers ----------
__device__ __forceinline__ u64 pack2f(float lo, float hi) {
    u64 r;
    asm("mov.b64 %0, {%1, %2};" : "=l"(r)
        : "r"(__float_as_uint(lo)), "r"(__float_as_uint(hi)));
    return r;
}
__device__ __forceinline__ void unpack2f(u64 v, float& lo, float& hi) {
    unsigned a, b;
    asm("mov.b64 {%0, %1}, %2;" : "=r"(a), "=r"(b) : "l"(v));
    lo = __uint_as_float(a); hi = __uint_as_float(b);
}
__device__ __forceinline__ u64 ffma2(u64 a, u64 b, u64 c) {
    u64 d;
    asm("fma.rn.f32x2 %0, %1, %2, %3;" : "=l"(d) : "l"(a), "l"(b), "l"(c));
    return d;
}
__device__ __forceinline__ u64 fadd2(u64 a, u64 b) {
    u64 d;
    asm("add.rn.f32x2 %0, %1, %2;" : "=l"(d) : "l"(a), "l"(b));
    return d;
}
__device__ __forceinline__ u64 mulwide(unsigned x, unsigned m) {
    u64 d;
    asm("mul.wide.u32 %0, %1, %2;" : "=l"(d) : "r"(x), "r"(m));
    return d;
}

// ---------- partitionable-threefry, ILP-2, mixed SHF / IMAD.WIDE rotates ----------
// JAX (jax_threefry_partitionable=True): counter (0, i), key (0, 42),
// bits32 = o0 ^ o1 of a single threefry2x32-20.
__device__ __forceinline__ uint2 tf2(unsigned i0, unsigned i1,
                                     unsigned m26, unsigned m6,
                                     unsigned m16, unsigned m24) {
    const unsigned ks1 = 42u, ks2 = 0x1BD11BF0u;  // 0x1BD11BDA ^ 0 ^ 42
    unsigned a0 = 0u, a1 = i0 + ks1;
    unsigned b0 = 0u, b1 = i1 + ks1;
#define SHFR2(R) { a0 += a1; b0 += b1;                                     \
                   a1 = __funnelshift_l(a1, a1, (R)) ^ a0;                 \
                   b1 = __funnelshift_l(b1, b1, (R)) ^ b0; }
#define MULR2(M) { a0 += a1; b0 += b1;                                     \
                   u64 wa = mulwide(a1, (M));                              \
                   u64 wb = mulwide(b1, (M));                              \
                   a1 = (unsigned)wa ^ (unsigned)(wa >> 32) ^ a0;          \
                   b1 = (unsigned)wb ^ (unsigned)(wb >> 32) ^ b0; }
    SHFR2(13) SHFR2(15) MULR2(m26) MULR2(m6)
    a0 += ks1; b0 += ks1;   a1 += ks2 + 1u; b1 += ks2 + 1u;
    SHFR2(17) SHFR2(29) MULR2(m16) MULR2(m24)
    a0 += ks2; b0 += ks2;   a1 += 2u;       b1 += 2u;        // ks0 + 2
    SHFR2(13) SHFR2(15) MULR2(m26) MULR2(m6)
    /* += ks0(0) */         a1 += ks1 + 3u; b1 += ks1 + 3u;
    SHFR2(17) SHFR2(29) MULR2(m16) MULR2(m24)
    a0 += ks1; b0 += ks1;   a1 += ks2 + 4u; b1 += ks2 + 4u;
    SHFR2(13) SHFR2(15) MULR2(m26) MULR2(m6)
    a0 += ks2; b0 += ks2;   a1 += 5u;       b1 += 5u;        // ks0 + 5
#undef SHFR2
#undef MULR2
    return make_uint2(a0 ^ a1, b0 ^ b1);
}

// ---------- k0: transpose A -> At, B*(2/0.9) -> Bt ----------
__global__ void k0_transpose(const float* __restrict__ A, const float* __restrict__ B) {
    const float CMUL = 2.0f / 0.9f;   // scaling / keep, folded into Bt
    int idx = blockIdx.x * blockDim.x + threadIdx.x;   // 0..4095
    if (idx < IN_F) {
#pragma unroll
        for (int r = 0; r < RANK_; ++r)
            g_At[idx * RANK_ + r] = A[r * IN_F + idx];
    }
    if (idx < OUT_F) {
#pragma unroll
        for (int r = 0; r < RANK_; ++r)
            g_Bt[r * OUT_F + idx] = B[idx * RANK_ + r] * CMUL;
    }
}

// ---------- k1: T = x @ A^T ----------
// 256 threads (8 warps), 16 rows/block, 2 rows/warp -> 16 u64 accumulators.
__global__ void __launch_bounds__(256, 3) k1_xa(const float* __restrict__ x) {
    __shared__ float x_s[BM1][KC];          // 8 KB
    __shared__ u64   At_s2[RANK_ / 2][KC];  // 8 KB

    const int tid  = threadIdx.x;
    const int wid  = tid >> 5;   // 0..7, warp owns rows {2w, 2w+1}
    const int lane = tid & 31;
    const int m0   = blockIdx.x * BM1;

    u64 acc2[2][8];
#pragma unroll
    for (int mi = 0; mi < 2; ++mi)
#pragma unroll
        for (int rr = 0; rr < 8; ++rr) acc2[mi][rr] = 0ull;

    for (int c = 0; c < IN_F / KC; ++c) {
        const float4* xg = reinterpret_cast<const float4*>(x + (size_t)m0 * IN_F + c * KC);
#pragma unroll
        for (int i = 0; i < 2; ++i) {
            int idx4 = tid + 256 * i;          // 0..511 float4s (16 x 32)
            int row  = idx4 >> 5;
            int col4 = idx4 & 31;
            float4 v = xg[(size_t)row * (IN_F / 4) + col4];
            *reinterpret_cast<float4*>(&x_s[row][col4 * 4]) = v;
        }
        if (tid < KC) {
            const float4* ag = reinterpret_cast<const float4*>(g_At + (size_t)(c * KC + tid) * RANK_);
            float4 a0 = ag[0], a1 = ag[1], a2v = ag[2], a3 = ag[3];
            At_s2[0][tid] = pack2f(a0.x,  a0.y);
            At_s2[1][tid] = pack2f(a0.z,  a0.w);
            At_s2[2][tid] = pack2f(a1.x,  a1.y);
            At_s2[3][tid] = pack2f(a1.z,  a1.w);
            At_s2[4][tid] = pack2f(a2v.x, a2v.y);
            At_s2[5][tid] = pack2f(a2v.z, a2v.w);
            At_s2[6][tid] = pack2f(a3.x,  a3.y);
            At_s2[7][tid] = pack2f(a3.z,  a3.w);
        }
        __syncthreads();

#pragma unroll
        for (int s = 0; s < KC / 32; ++s) {
            int k = lane + 32 * s;
            u64 a2[8];
#pragma unroll
            for (int rr = 0; rr < 8; ++rr) a2[rr] = At_s2[rr][k];
#pragma unroll
            for (int mi = 0; mi < 2; ++mi) {
                float xv = x_s[wid * 2 + mi][k];
                u64 xx = pack2f(xv, xv);
#pragma unroll
                for (int rr = 0; rr < 8; ++rr)
                    acc2[mi][rr] = ffma2(xx, a2[rr], acc2[mi][rr]);
            }
        }
        __syncthreads();
    }

    // butterfly reduce across 32 k-lanes
#pragma unroll
    for (int off = 16; off > 0; off >>= 1) {
#pragma unroll
        for (int mi = 0; mi < 2; ++mi)
#pragma unroll
            for (int rr = 0; rr < 8; ++rr) {
                u64 o = __shfl_xor_sync(0xffffffffu, acc2[mi][rr], off);
                acc2[mi][rr] = fadd2(acc2[mi][rr], o);
            }
    }
    if (lane < RANK_) {
#pragma unroll
        for (int mi = 0; mi < 2; ++mi) {
            float lo, hi;
            unpack2f(acc2[mi][lane >> 1], lo, hi);
            float v = (lane & 1) ? hi : lo;
            g_T2[(size_t)(m0 + wid * 2 + mi) * RANK_ + lane] = pack2f(v, v);
        }
    }
}

// ---------- k2: y = dropout( T @ Bt ), ILP-2 mixed-pipe threefry ----------
__global__ void __launch_bounds__(256, 3) k2_by(float* __restrict__ y) {
    __shared__ u64 B_s[RANK_][CBT / 2];  // 32 KB, col pairs
    __shared__ u64 T_s[RB][RANK_];       // 2 KB, (t,t) packed

    const int tid   = threadIdx.x;
    const int cb    = (blockIdx.x & 7) * CBT;           // col tile 0..7
    const int rbase = (blockIdx.x >> 3) * RB;           // row tile

    // opaque rotate multipliers (one LDG, hoisted)
    const uint4 mm = *reinterpret_cast<const uint4*>(g_mul);

    // stage Bt slice: 16 x 512 floats, coalesced float4
#pragma unroll
    for (int i = 0; i < 8; ++i) {
        int idx4 = tid + 256 * i;          // 0..2047 float4s
        int r    = idx4 >> 7;              // 128 float4 per row
        int c4   = idx4 & 127;
        float4 v = *reinterpret_cast<const float4*>(&g_Bt[r * OUT_F + cb + c4 * 4]);
        B_s[r][c4 * 2]     = pack2f(v.x, v.y);
        B_s[r][c4 * 2 + 1] = pack2f(v.z, v.w);
    }
    // stage T rows (already packed (v,v) by k1)
    {
        int row = tid >> 4;                // 0..15
        int r   = tid & 15;
        T_s[row][r] = g_T2[(size_t)(rbase + row) * RANK_ + r];
    }
    __syncthreads();

    // this thread's B column-pair, held across all rows
    u64 b[RANK_];
#pragma unroll
    for (int r = 0; r < RANK_; ++r) b[r] = B_s[r][tid];

#pragma unroll 1
    for (int q = 0; q < RB; ++q) {
        u64 acc = 0ull;
#pragma unroll
        for (int rp = 0; rp < RANK_ / 2; ++rp) {
            ulonglong2 t2 = *reinterpret_cast<const ulonglong2*>(&T_s[q][rp * 2]);
            acc = ffma2(t2.x, b[rp * 2],     acc);
            acc = ffma2(t2.y, b[rp * 2 + 1], acc);
        }
        float v0, v1;
        unpack2f(acc, v0, v1);

        const int m = rbase + q;
        unsigned base_i = (unsigned)m * 4096u + (unsigned)(cb + tid * 2);
        uint2 bb = tf2(base_i, base_i + 1u, mm.x, mm.y, mm.z, mm.w);
        float o0 = (bb.x < TH_) ? v0 : 0.0f;
        float o1 = (bb.y < TH_) ? v1 : 0.0f;
        *reinterpret_cast<float2*>(&y[(size_t)m * 4096 + cb + tid * 2]) =
            make_float2(o0, o1);
    }
}

extern "C" void kernel_launch(void* const* d_in, const int* in_sizes, int n_in,
                              void* d_out, int out_size) {
    const float* x = (const float*)d_in[0];
    const float* A = (const float*)d_in[1];
    const float* B = (const float*)d_in[2];
    float*       y = (float*)d_out;

    k0_transpose<<<16, 256>>>(A, B);
    k1_xa<<<MROWS / BM1, 256>>>(x);
    k2_by<<<(MROWS / RB) * (OUT_F / CBT), 256>>>(y);
}

// round 7
// speedup vs baseline: 1.0731x; 1.0731x over previous
#include <cuda_runtime.h>
#include <stdint.h>

#define IN_F   4096
#define OUT_F  4096
#define RANK_  16
#define MROWS  16384            // 4*4096 flattened rows
#define TH_    0xE6666600u      // bits < TH_  <=>  uniform(bits) < 0.9f (exact)
#define KC     128              // k-chunk (k1)
#define BM1    16               // rows per block (k1)
#define RB     16               // rows per block (k2)
#define CBT    512              // col-chunk (k2)

typedef unsigned long long u64;

// scratch (allocation-free rule: __device__ global)
static __device__ u64 g_T2[MROWS * RANK_];  // T packed as (v,v) f32x2, CMUL folded

// ---------- f32x2 helpers ----------
__device__ __forceinline__ u64 pack2f(float lo, float hi) {
    u64 r;
    asm("mov.b64 %0, {%1, %2};" : "=l"(r)
        : "r"(__float_as_uint(lo)), "r"(__float_as_uint(hi)));
    return r;
}
__device__ __forceinline__ void unpack2f(u64 v, float& lo, float& hi) {
    unsigned a, b;
    asm("mov.b64 {%0, %1}, %2;" : "=r"(a), "=r"(b) : "l"(v));
    lo = __uint_as_float(a); hi = __uint_as_float(b);
}
__device__ __forceinline__ u64 ffma2(u64 a, u64 b, u64 c) {
    u64 d;
    asm("fma.rn.f32x2 %0, %1, %2, %3;" : "=l"(d) : "l"(a), "l"(b), "l"(c));
    return d;
}
__device__ __forceinline__ u64 fadd2(u64 a, u64 b) {
    u64 d;
    asm("add.rn.f32x2 %0, %1, %2;" : "=l"(d) : "l"(a), "l"(b));
    return d;
}

// ---------- partitionable-threefry bits for flat index i ----------
// JAX (jax_threefry_partitionable=True): counter (0, i), key (0, 42),
// bits32 = o0 ^ o1 of a single threefry2x32-20. Named scalars only.
__device__ __forceinline__ unsigned tf_bits(unsigned i) {
    const unsigned ks1 = 42u, ks2 = 0x1BD11BF0u;  // 0x1BD11BDA ^ 0 ^ 42
    unsigned x0 = 0u;          // counter_hi(0) + ks0(0)
    unsigned x1 = i + ks1;     // counter_lo + ks1
#define TF_RND(R) { x0 += x1; x1 = __funnelshift_l(x1, x1, (R)); x1 ^= x0; }
    TF_RND(13) TF_RND(15) TF_RND(26) TF_RND(6)
    x0 += ks1;              x1 += ks2 + 1u;
    TF_RND(17) TF_RND(29) TF_RND(16) TF_RND(24)
    x0 += ks2;              x1 += 2u;              // ks0 + 2
    TF_RND(13) TF_RND(15) TF_RND(26) TF_RND(6)
    /* x0 += ks0(=0) */     x1 += ks1 + 3u;
    TF_RND(17) TF_RND(29) TF_RND(16) TF_RND(24)
    x0 += ks1;              x1 += ks2 + 4u;
    TF_RND(13) TF_RND(15) TF_RND(26) TF_RND(6)
    x0 += ks2;              x1 += 5u;              // ks0 + 5
#undef TF_RND
    return x0 ^ x1;
}

// ---------- k1: T = x @ A^T  (A transposed in-kernel; CMUL folded into T) ----------
// 256 threads (8 warps), 16 rows/block, 2 rows/warp -> 16 u64 accumulators.
__global__ void __launch_bounds__(256, 3) k1_xa(const float* __restrict__ x,
                                                const float* __restrict__ A) {
    __shared__ float x_s[BM1][KC];          // 8 KB
    __shared__ u64   At_s2[RANK_ / 2][KC];  // 8 KB, (r even, r odd) pairs

    const int tid  = threadIdx.x;
    const int wid  = tid >> 5;   // 0..7, warp owns rows {2w, 2w+1}
    const int lane = tid & 31;
    const int m0   = blockIdx.x * BM1;

    // A-tile loader mapping: thread owns column k, half of the 16 r-rows
    const int ak   = tid & 127;          // 0..127
    const int ahalf = tid >> 7;          // 0 -> r 0..7, 1 -> r 8..15

    u64 acc2[2][8];
#pragma unroll
    for (int mi = 0; mi < 2; ++mi)
#pragma unroll
        for (int rr = 0; rr < 8; ++rr) acc2[mi][rr] = 0ull;

    for (int c = 0; c < IN_F / KC; ++c) {
        // x tile: 16 x 128 floats, coalesced float4
        const float4* xg = reinterpret_cast<const float4*>(x + (size_t)m0 * IN_F + c * KC);
#pragma unroll
        for (int i = 0; i < 2; ++i) {
            int idx4 = tid + 256 * i;          // 0..511 float4s
            int row  = idx4 >> 5;
            int col4 = idx4 & 31;
            float4 v = xg[(size_t)row * (IN_F / 4) + col4];
            *reinterpret_cast<float4*>(&x_s[row][col4 * 4]) = v;
        }
        // A tile: read 8 rows at column (c*KC + ak), pack r-pairs (L2-resident)
        {
            const float* ap = A + (size_t)(ahalf * 8) * IN_F + c * KC + ak;
            float v0 = ap[0];
            float v1 = ap[IN_F];
            float v2 = ap[2 * IN_F];
            float v3 = ap[3 * IN_F];
            float v4 = ap[4 * IN_F];
            float v5 = ap[5 * IN_F];
            float v6 = ap[6 * IN_F];
            float v7 = ap[7 * IN_F];
            At_s2[ahalf * 4 + 0][ak] = pack2f(v0, v1);
            At_s2[ahalf * 4 + 1][ak] = pack2f(v2, v3);
            At_s2[ahalf * 4 + 2][ak] = pack2f(v4, v5);
            At_s2[ahalf * 4 + 3][ak] = pack2f(v6, v7);
        }
        __syncthreads();

#pragma unroll
        for (int s = 0; s < KC / 32; ++s) {
            int k = lane + 32 * s;
            u64 a2[8];
#pragma unroll
            for (int rr = 0; rr < 8; ++rr) a2[rr] = At_s2[rr][k];
#pragma unroll
            for (int mi = 0; mi < 2; ++mi) {
                float xv = x_s[wid * 2 + mi][k];
                u64 xx = pack2f(xv, xv);
#pragma unroll
                for (int rr = 0; rr < 8; ++rr)
                    acc2[mi][rr] = ffma2(xx, a2[rr], acc2[mi][rr]);
            }
        }
        __syncthreads();
    }

    // butterfly reduce across 32 k-lanes
#pragma unroll
    for (int off = 16; off > 0; off >>= 1) {
#pragma unroll
        for (int mi = 0; mi < 2; ++mi)
#pragma unroll
            for (int rr = 0; rr < 8; ++rr) {
                u64 o = __shfl_xor_sync(0xffffffffu, acc2[mi][rr], off);
                acc2[mi][rr] = fadd2(acc2[mi][rr], o);
            }
    }
    if (lane < RANK_) {
        const float CMUL = 2.0f / 0.9f;   // scaling / keep, folded into T
#pragma unroll
        for (int mi = 0; mi < 2; ++mi) {
            float lo, hi;
            unpack2f(acc2[mi][lane >> 1], lo, hi);
            float v = ((lane & 1) ? hi : lo) * CMUL;
            g_T2[(size_t)(m0 + wid * 2 + mi) * RANK_ + lane] = pack2f(v, v);
        }
    }
}

// ---------- k2: y = dropout( T @ B^T ), Bt built from B in-kernel ----------
__global__ void __launch_bounds__(256) k2_by(const float* __restrict__ B,
                                             float* __restrict__ y) {
    __shared__ u64 B_s[RANK_][CBT / 2];  // 32 KB, col pairs (o even, o odd)
    __shared__ u64 T_s[RB][RANK_];       // 2 KB, (t,t) packed

    const int tid   = threadIdx.x;
    const int cb    = (blockIdx.x & 7) * CBT;           // col tile 0..7
    const int rbase = (blockIdx.x >> 3) * RB;           // row tile

    // stage B slice: thread t owns output cols {cb+2t, cb+2t+1}; their B rows
    // are contiguous 128 bytes -> 8 coalesced float4 loads, zero shuffles.
    {
        const float4* bp = reinterpret_cast<const float4*>(B + (size_t)(cb + 2 * tid) * RANK_);
        float4 r0 = bp[0], r1 = bp[1], r2 = bp[2], r3 = bp[3];   // row o = cb+2t
        float4 s0 = bp[4], s1 = bp[5], s2 = bp[6], s3 = bp[7];   // row o = cb+2t+1
        B_s[ 0][tid] = pack2f(r0.x, s0.x);
        B_s[ 1][tid] = pack2f(r0.y, s0.y);
        B_s[ 2][tid] = pack2f(r0.z, s0.z);
        B_s[ 3][tid] = pack2f(r0.w, s0.w);
        B_s[ 4][tid] = pack2f(r1.x, s1.x);
        B_s[ 5][tid] = pack2f(r1.y, s1.y);
        B_s[ 6][tid] = pack2f(r1.z, s1.z);
        B_s[ 7][tid] = pack2f(r1.w, s1.w);
        B_s[ 8][tid] = pack2f(r2.x, s2.x);
        B_s[ 9][tid] = pack2f(r2.y, s2.y);
        B_s[10][tid] = pack2f(r2.z, s2.z);
        B_s[11][tid] = pack2f(r2.w, s2.w);
        B_s[12][tid] = pack2f(r3.x, s3.x);
        B_s[13][tid] = pack2f(r3.y, s3.y);
        B_s[14][tid] = pack2f(r3.z, s3.z);
        B_s[15][tid] = pack2f(r3.w, s3.w);
    }
    // stage T rows (packed (v,v), CMUL already folded)
    {
        int row = tid >> 4;                // 0..15
        int r   = tid & 15;
        T_s[row][r] = g_T2[(size_t)(rbase + row) * RANK_ + r];
    }
    __syncthreads();

    // this thread's B column-pair, held across all rows
    u64 b[RANK_];
#pragma unroll
    for (int r = 0; r < RANK_; ++r) b[r] = B_s[r][tid];

#pragma unroll 1
    for (int q = 0; q < RB; ++q) {
        u64 acc = 0ull;
#pragma unroll
        for (int rp = 0; rp < RANK_ / 2; ++rp) {
            ulonglong2 t2 = *reinterpret_cast<const ulonglong2*>(&T_s[q][rp * 2]);
            acc = ffma2(t2.x, b[rp * 2],     acc);
            acc = ffma2(t2.y, b[rp * 2 + 1], acc);
        }
        float v0, v1;
        unpack2f(acc, v0, v1);

        const int m = rbase + q;
        unsigned base_i = (unsigned)m * 4096u + (unsigned)(cb + tid * 2);
        unsigned bits0 = tf_bits(base_i);
        unsigned bits1 = tf_bits(base_i + 1u);
        float o0 = (bits0 < TH_) ? v0 : 0.0f;
        float o1 = (bits1 < TH_) ? v1 : 0.0f;
        *reinterpret_cast<float2*>(&y[(size_t)m * 4096 + cb + tid * 2]) =
            make_float2(o0, o1);
    }
}

extern "C" void kernel_launch(void* const* d_in, const int* in_sizes, int n_in,
                              void* d_out, int out_size) {
    const float* x = (const float*)d_in[0];
    const float* A = (const float*)d_in[1];
    const float* B = (const float*)d_in[2];
    float*       y = (float*)d_out;

    k1_xa<<<MROWS / BM1, 256>>>(x, A);
    k2_by<<<(MROWS / RB) * (OUT_F / CBT), 256>>>(B, y);
}

// round 8
// speedup vs baseline: 1.1343x; 1.0570x over previous
#include <cuda_runtime.h>
#include <stdint.h>

#define IN_F   4096
#define OUT_F  4096
#define RANK_  16
#define MROWS  16384            // 4*4096 flattened rows
#define TH_    0xE6666600u      // bits < TH_  <=>  uniform(bits) < 0.9f (exact)
#define KC     128              // k-chunk (k1)
#define BM1    32               // rows per block (k1): 8 warps x 4 rows
#define RB     16               // rows per block (k2)
#define CBT    512              // col-chunk (k2)

typedef unsigned long long u64;

// scratch (allocation-free rule: __device__ global)
static __device__ u64 g_T2[MROWS * RANK_];  // T packed as (v,v) f32x2, CMUL folded

// ---------- f32x2 helpers ----------
__device__ __forceinline__ u64 pack2f(float lo, float hi) {
    u64 r;
    asm("mov.b64 %0, {%1, %2};" : "=l"(r)
        : "r"(__float_as_uint(lo)), "r"(__float_as_uint(hi)));
    return r;
}
__device__ __forceinline__ void unpack2f(u64 v, float& lo, float& hi) {
    unsigned a, b;
    asm("mov.b64 {%0, %1}, %2;" : "=r"(a), "=r"(b) : "l"(v));
    lo = __uint_as_float(a); hi = __uint_as_float(b);
}
__device__ __forceinline__ u64 ffma2(u64 a, u64 b, u64 c) {
    u64 d;
    asm("fma.rn.f32x2 %0, %1, %2, %3;" : "=l"(d) : "l"(a), "l"(b), "l"(c));
    return d;
}
__device__ __forceinline__ u64 fadd2(u64 a, u64 b) {
    u64 d;
    asm("add.rn.f32x2 %0, %1, %2;" : "=l"(d) : "l"(a), "l"(b));
    return d;
}

// ---------- partitionable-threefry, 4 interleaved instances, NAMED scalars ----------
// JAX (jax_threefry_partitionable=True): counter (0, i), key (0, 42),
// bits32 = o0 ^ o1 of a single threefry2x32-20.
__device__ __forceinline__ uint4 tf4(unsigned i0, unsigned i1,
                                     unsigned i2, unsigned i3) {
    const unsigned ks1 = 42u, ks2 = 0x1BD11BF0u;  // 0x1BD11BDA ^ 0 ^ 42
    unsigned a0 = 0u, a1 = i0 + ks1;
    unsigned b0 = 0u, b1 = i1 + ks1;
    unsigned c0 = 0u, c1 = i2 + ks1;
    unsigned d0 = 0u, d1 = i3 + ks1;
#define R4(R) { a0 += a1; b0 += b1; c0 += c1; d0 += d1;                    \
                a1 = __funnelshift_l(a1, a1, (R)) ^ a0;                    \
                b1 = __funnelshift_l(b1, b1, (R)) ^ b0;                    \
                c1 = __funnelshift_l(c1, c1, (R)) ^ c0;                    \
                d1 = __funnelshift_l(d1, d1, (R)) ^ d0; }
#define K4(C0, C1) { a0 += (C0); b0 += (C0); c0 += (C0); d0 += (C0);       \
                     a1 += (C1); b1 += (C1); c1 += (C1); d1 += (C1); }
#define K4B(C1)    { a1 += (C1); b1 += (C1); c1 += (C1); d1 += (C1); }
    R4(13) R4(15) R4(26) R4(6)
    K4(ks1, ks2 + 1u)
    R4(17) R4(29) R4(16) R4(24)
    K4(ks2, 2u)                   // ks0 + 2
    R4(13) R4(15) R4(26) R4(6)
    K4B(ks1 + 3u)                 // x0 += ks0(=0) elided
    R4(17) R4(29) R4(16) R4(24)
    K4(ks1, ks2 + 4u)
    R4(13) R4(15) R4(26) R4(6)
    K4(ks2, 5u)                   // ks0 + 5
#undef R4
#undef K4
#undef K4B
    return make_uint4(a0 ^ a1, b0 ^ b1, c0 ^ c1, d0 ^ d1);
}

// ---------- k1: T = x @ A^T  (A transposed in-kernel; CMUL folded into T) ----------
// 256 threads (8 warps), 32 rows/block, 4 rows/warp -> 64 u64 accumulator regs.
__global__ void __launch_bounds__(256, 2) k1_xa(const float* __restrict__ x,
                                                const float* __restrict__ A) {
    __shared__ float x_s[BM1][KC];          // 16 KB
    __shared__ u64   At_s2[RANK_ / 2][KC];  //  8 KB, (r even, r odd) pairs

    const int tid  = threadIdx.x;
    const int wid  = tid >> 5;   // 0..7, warp owns rows {4w..4w+3}
    const int lane = tid & 31;
    const int m0   = blockIdx.x * BM1;

    // A-tile loader mapping: thread owns column k, half of the 16 r-rows
    const int ak    = tid & 127;         // 0..127
    const int ahalf = tid >> 7;          // 0 -> r 0..7, 1 -> r 8..15

    u64 acc2[4][8];
#pragma unroll
    for (int mi = 0; mi < 4; ++mi)
#pragma unroll
        for (int rr = 0; rr < 8; ++rr) acc2[mi][rr] = 0ull;

    for (int c = 0; c < IN_F / KC; ++c) {
        // x tile: 32 x 128 floats, coalesced float4
        const float4* xg = reinterpret_cast<const float4*>(x + (size_t)m0 * IN_F + c * KC);
#pragma unroll
        for (int i = 0; i < 4; ++i) {
            int idx4 = tid + 256 * i;          // 0..1023 float4s
            int row  = idx4 >> 5;
            int col4 = idx4 & 31;
            float4 v = xg[(size_t)row * (IN_F / 4) + col4];
            *reinterpret_cast<float4*>(&x_s[row][col4 * 4]) = v;
        }
        // A tile: read 8 rows at column (c*KC + ak), pack r-pairs (L2-resident)
        {
            const float* ap = A + (size_t)(ahalf * 8) * IN_F + c * KC + ak;
            float v0 = ap[0];
            float v1 = ap[IN_F];
            float v2 = ap[2 * IN_F];
            float v3 = ap[3 * IN_F];
            float v4 = ap[4 * IN_F];
            float v5 = ap[5 * IN_F];
            float v6 = ap[6 * IN_F];
            float v7 = ap[7 * IN_F];
            At_s2[ahalf * 4 + 0][ak] = pack2f(v0, v1);
            At_s2[ahalf * 4 + 1][ak] = pack2f(v2, v3);
            At_s2[ahalf * 4 + 2][ak] = pack2f(v4, v5);
            At_s2[ahalf * 4 + 3][ak] = pack2f(v6, v7);
        }
        __syncthreads();

#pragma unroll
        for (int s = 0; s < KC / 32; ++s) {
            int k = lane + 32 * s;
            u64 a2[8];
#pragma unroll
            for (int rr = 0; rr < 8; ++rr) a2[rr] = At_s2[rr][k];
#pragma unroll
            for (int mi = 0; mi < 4; ++mi) {
                float xv = x_s[wid * 4 + mi][k];
                u64 xx = pack2f(xv, xv);
#pragma unroll
                for (int rr = 0; rr < 8; ++rr)
                    acc2[mi][rr] = ffma2(xx, a2[rr], acc2[mi][rr]);
            }
        }
        __syncthreads();
    }

    // butterfly reduce across 32 k-lanes
#pragma unroll
    for (int off = 16; off > 0; off >>= 1) {
#pragma unroll
        for (int mi = 0; mi < 4; ++mi)
#pragma unroll
            for (int rr = 0; rr < 8; ++rr) {
                u64 o = __shfl_xor_sync(0xffffffffu, acc2[mi][rr], off);
                acc2[mi][rr] = fadd2(acc2[mi][rr], o);
            }
    }
    if (lane < RANK_) {
        const float CMUL = 2.0f / 0.9f;   // scaling / keep, folded into T
#pragma unroll
        for (int mi = 0; mi < 4; ++mi) {
            float lo, hi;
            unpack2f(acc2[mi][lane >> 1], lo, hi);
            float v = ((lane & 1) ? hi : lo) * CMUL;
            g_T2[(size_t)(m0 + wid * 4 + mi) * RANK_ + lane] = pack2f(v, v);
        }
    }
}

// ---------- k2: y = dropout( T @ B^T ), 2 rows/iter, ILP-4 threefry ----------
__global__ void __launch_bounds__(256, 4) k2_by(const float* __restrict__ B,
                                                float* __restrict__ y) {
    __shared__ u64 B_s[RANK_][CBT / 2];  // 32 KB, col pairs (o even, o odd)
    __shared__ u64 T_s[RB][RANK_];       // 2 KB, (t,t) packed

    const int tid   = threadIdx.x;
    const int cb    = (blockIdx.x & 7) * CBT;           // col tile 0..7
    const int rbase = (blockIdx.x >> 3) * RB;           // row tile

    // stage B slice: thread t owns output cols {cb+2t, cb+2t+1}; their B rows
    // are contiguous 128 bytes -> 8 coalesced float4 loads, zero shuffles.
    {
        const float4* bp = reinterpret_cast<const float4*>(B + (size_t)(cb + 2 * tid) * RANK_);
        float4 r0 = bp[0], r1 = bp[1], r2 = bp[2], r3 = bp[3];   // row o = cb+2t
        float4 s0 = bp[4], s1 = bp[5], s2 = bp[6], s3 = bp[7];   // row o = cb+2t+1
        B_s[ 0][tid] = pack2f(r0.x, s0.x);
        B_s[ 1][tid] = pack2f(r0.y, s0.y);
        B_s[ 2][tid] = pack2f(r0.z, s0.z);
        B_s[ 3][tid] = pack2f(r0.w, s0.w);
        B_s[ 4][tid] = pack2f(r1.x, s1.x);
        B_s[ 5][tid] = pack2f(r1.y, s1.y);
        B_s[ 6][tid] = pack2f(r1.z, s1.z);
        B_s[ 7][tid] = pack2f(r1.w, s1.w);
        B_s[ 8][tid] = pack2f(r2.x, s2.x);
        B_s[ 9][tid] = pack2f(r2.y, s2.y);
        B_s[10][tid] = pack2f(r2.z, s2.z);
        B_s[11][tid] = pack2f(r2.w, s2.w);
        B_s[12][tid] = pack2f(r3.x, s3.x);
        B_s[13][tid] = pack2f(r3.y, s3.y);
        B_s[14][tid] = pack2f(r3.z, s3.z);
        B_s[15][tid] = pack2f(r3.w, s3.w);
    }
    // stage T rows (packed (v,v), CMUL already folded)
    {
        int row = tid >> 4;                // 0..15
        int r   = tid & 15;
        T_s[row][r] = g_T2[(size_t)(rbase + row) * RANK_ + r];
    }
    __syncthreads();

    // this thread's B column-pair, held across all rows
    u64 b[RANK_];
#pragma unroll
    for (int r = 0; r < RANK_; ++r) b[r] = B_s[r][tid];

#pragma unroll 1
    for (int q = 0; q < RB; q += 2) {
        u64 accA = 0ull, accB = 0ull;
#pragma unroll
        for (int rp = 0; rp < RANK_ / 2; ++rp) {
            ulonglong2 tA = *reinterpret_cast<const ulonglong2*>(&T_s[q][rp * 2]);
            ulonglong2 tB = *reinterpret_cast<const ulonglong2*>(&T_s[q + 1][rp * 2]);
            accA = ffma2(tA.x, b[rp * 2],     accA);
            accA = ffma2(tA.y, b[rp * 2 + 1], accA);
            accB = ffma2(tB.x, b[rp * 2],     accB);
            accB = ffma2(tB.y, b[rp * 2 + 1], accB);
        }
        float v0, v1, v2, v3;
        unpack2f(accA, v0, v1);
        unpack2f(accB, v2, v3);

        const int m = rbase + q;
        unsigned base_i = (unsigned)m * 4096u + (unsigned)(cb + tid * 2);
        uint4 bb = tf4(base_i, base_i + 1u, base_i + 4096u, base_i + 4097u);
        float o0 = (bb.x < TH_) ? v0 : 0.0f;
        float o1 = (bb.y < TH_) ? v1 : 0.0f;
        float o2 = (bb.z < TH_) ? v2 : 0.0f;
        float o3 = (bb.w < TH_) ? v3 : 0.0f;
        *reinterpret_cast<float2*>(&y[(size_t)m * 4096 + cb + tid * 2]) =
            make_float2(o0, o1);
        *reinterpret_cast<float2*>(&y[(size_t)(m + 1) * 4096 + cb + tid * 2]) =
            make_float2(o2, o3);
    }
}

extern "C" void kernel_launch(void* const* d_in, const int* in_sizes, int n_in,
                              void* d_out, int out_size) {
    const float* x = (const float*)d_in[0];
    const float* A = (const float*)d_in[1];
    const float* B = (const float*)d_in[2];
    float*       y = (float*)d_out;

    k1_xa<<<MROWS / BM1, 256>>>(x, A);
    k2_by<<<(MROWS / RB) * (OUT_F / CBT), 256>>>(B, y);
}

// round 9
// speedup vs baseline: 1.2370x; 1.0906x over previous
#include <cuda_runtime.h>
#include <stdint.h>

#define IN_F   4096
#define OUT_F  4096
#define RANK_  16
#define MROWS  16384            // 4*4096 flattened rows
#define TH_    0xE6666600u      // bits < TH_  <=>  uniform(bits) < 0.9f (exact)
#define KC     128              // k-chunk (k1)
#define NC     (IN_F / KC)      // 32 chunks
#define BM1    32               // rows per block (k1): 8 warps x 4 rows
#define RB     64               // rows per block (k2)
#define CBT    512              // col-chunk (k2)

typedef unsigned long long u64;

// scratch (allocation-free rule: __device__ global)
static __device__ u64 g_T2[MROWS * RANK_];  // T packed as (v,v) f32x2, CMUL folded

// ---------- f32x2 helpers ----------
__device__ __forceinline__ u64 pack2f(float lo, float hi) {
    u64 r;
    asm("mov.b64 %0, {%1, %2};" : "=l"(r)
        : "r"(__float_as_uint(lo)), "r"(__float_as_uint(hi)));
    return r;
}
__device__ __forceinline__ void unpack2f(u64 v, float& lo, float& hi) {
    unsigned a, b;
    asm("mov.b64 {%0, %1}, %2;" : "=r"(a), "=r"(b) : "l"(v));
    lo = __uint_as_float(a); hi = __uint_as_float(b);
}
__device__ __forceinline__ u64 ffma2(u64 a, u64 b, u64 c) {
    u64 d;
    asm("fma.rn.f32x2 %0, %1, %2, %3;" : "=l"(d) : "l"(a), "l"(b), "l"(c));
    return d;
}
__device__ __forceinline__ u64 fadd2(u64 a, u64 b) {
    u64 d;
    asm("add.rn.f32x2 %0, %1, %2;" : "=l"(d) : "l"(a), "l"(b));
    return d;
}

// ---------- partitionable-threefry, 4 interleaved instances, NAMED scalars ----------
// JAX (jax_threefry_partitionable=True): counter (0, i), key (0, 42),
// bits32 = o0 ^ o1 of a single threefry2x32-20.
__device__ __forceinline__ uint4 tf4(unsigned i0, unsigned i1,
                                     unsigned i2, unsigned i3) {
    const unsigned ks1 = 42u, ks2 = 0x1BD11BF0u;  // 0x1BD11BDA ^ 0 ^ 42
    unsigned a0 = 0u, a1 = i0 + ks1;
    unsigned b0 = 0u, b1 = i1 + ks1;
    unsigned c0 = 0u, c1 = i2 + ks1;
    unsigned d0 = 0u, d1 = i3 + ks1;
#define R4(R) { a0 += a1; b0 += b1; c0 += c1; d0 += d1;                    \
                a1 = __funnelshift_l(a1, a1, (R)) ^ a0;                    \
                b1 = __funnelshift_l(b1, b1, (R)) ^ b0;                    \
                c1 = __funnelshift_l(c1, c1, (R)) ^ c0;                    \
                d1 = __funnelshift_l(d1, d1, (R)) ^ d0; }
#define K4(C0, C1) { a0 += (C0); b0 += (C0); c0 += (C0); d0 += (C0);       \
                     a1 += (C1); b1 += (C1); c1 += (C1); d1 += (C1); }
#define K4B(C1)    { a1 += (C1); b1 += (C1); c1 += (C1); d1 += (C1); }
    R4(13) R4(15) R4(26) R4(6)
    K4(ks1, ks2 + 1u)
    R4(17) R4(29) R4(16) R4(24)
    K4(ks2, 2u)                   // ks0 + 2
    R4(13) R4(15) R4(26) R4(6)
    K4B(ks1 + 3u)                 // x0 += ks0(=0) elided
    R4(17) R4(29) R4(16) R4(24)
    K4(ks1, ks2 + 4u)
    R4(13) R4(15) R4(26) R4(6)
    K4(ks2, 5u)                   // ks0 + 5
#undef R4
#undef K4
#undef K4B
    return make_uint4(a0 ^ a1, b0 ^ b1, c0 ^ c1, d0 ^ d1);
}

// ---------- k1: T = x @ A^T, software-pipelined double-buffered smem ----------
// 256 threads (8 warps), 32 rows/block, 4 rows/warp -> 64 u64 accumulator regs.
__global__ void __launch_bounds__(256, 2) k1_xa(const float* __restrict__ x,
                                                const float* __restrict__ A) {
    __shared__ float x_s[2][BM1][KC];              // 32 KB
    __shared__ u64   At_s2[2][RANK_ / 2][KC];      // 16 KB

    const int tid  = threadIdx.x;
    const int wid  = tid >> 5;   // 0..7, warp owns rows {4w..4w+3}
    const int lane = tid & 31;
    const int m0   = blockIdx.x * BM1;

    // tile-loader mapping
    const int lrow0 = tid >> 5;          // x rows: tid covers 8 rows x 32 col4s
    const int lcol4 = tid & 31;
    const int ak    = tid & 127;         // A col within chunk
    const int ahalf = tid >> 7;          // 0 -> r 0..7, 1 -> r 8..15

    u64 acc2[4][8];
#pragma unroll
    for (int mi = 0; mi < 4; ++mi)
#pragma unroll
        for (int rr = 0; rr < 8; ++rr) acc2[mi][rr] = 0ull;

    float4 xr[4];
    float  ar[8];

    // prologue: load tile 0 into regs, store to buf 0
    {
        const float4* xg = reinterpret_cast<const float4*>(x + (size_t)m0 * IN_F);
#pragma unroll
        for (int i = 0; i < 4; ++i)
            xr[i] = xg[(size_t)(lrow0 + 8 * i) * (IN_F / 4) + lcol4];
        const float* ap = A + (size_t)(ahalf * 8) * IN_F + ak;
#pragma unroll
        for (int j = 0; j < 8; ++j) ar[j] = ap[(size_t)j * IN_F];
    }
#pragma unroll
    for (int i = 0; i < 4; ++i)
        *reinterpret_cast<float4*>(&x_s[0][lrow0 + 8 * i][lcol4 * 4]) = xr[i];
#pragma unroll
    for (int j = 0; j < 4; ++j)
        At_s2[0][ahalf * 4 + j][ak] = pack2f(ar[2 * j], ar[2 * j + 1]);
    __syncthreads();

#pragma unroll 1
    for (int c = 0; c < NC; ++c) {
        const int buf = c & 1;
        // issue prefetch LDGs for tile c+1 (in flight during compute)
        if (c + 1 < NC) {
            const float4* xg = reinterpret_cast<const float4*>(
                x + (size_t)m0 * IN_F + (c + 1) * KC);
#pragma unroll
            for (int i = 0; i < 4; ++i)
                xr[i] = xg[(size_t)(lrow0 + 8 * i) * (IN_F / 4) + lcol4];
            const float* ap = A + (size_t)(ahalf * 8) * IN_F + (c + 1) * KC + ak;
#pragma unroll
            for (int j = 0; j < 8; ++j) ar[j] = ap[(size_t)j * IN_F];
        }

        // compute on tile c from smem (hides the prefetch latency)
#pragma unroll
        for (int s = 0; s < KC / 32; ++s) {
            int k = lane + 32 * s;
            u64 a2[8];
#pragma unroll
            for (int rr = 0; rr < 8; ++rr) a2[rr] = At_s2[buf][rr][k];
#pragma unroll
            for (int mi = 0; mi < 4; ++mi) {
                float xv = x_s[buf][wid * 4 + mi][k];
                u64 xx = pack2f(xv, xv);
#pragma unroll
                for (int rr = 0; rr < 8; ++rr)
                    acc2[mi][rr] = ffma2(xx, a2[rr], acc2[mi][rr]);
            }
        }

        // stage tile c+1 into the other buffer
        if (c + 1 < NC) {
            const int nbuf = buf ^ 1;
#pragma unroll
            for (int i = 0; i < 4; ++i)
                *reinterpret_cast<float4*>(&x_s[nbuf][lrow0 + 8 * i][lcol4 * 4]) = xr[i];
#pragma unroll
            for (int j = 0; j < 4; ++j)
                At_s2[nbuf][ahalf * 4 + j][ak] = pack2f(ar[2 * j], ar[2 * j + 1]);
            __syncthreads();
        }
    }

    // butterfly reduce across 32 k-lanes
#pragma unroll
    for (int off = 16; off > 0; off >>= 1) {
#pragma unroll
        for (int mi = 0; mi < 4; ++mi)
#pragma unroll
            for (int rr = 0; rr < 8; ++rr) {
                u64 o = __shfl_xor_sync(0xffffffffu, acc2[mi][rr], off);
                acc2[mi][rr] = fadd2(acc2[mi][rr], o);
            }
    }
    if (lane < RANK_) {
        const float CMUL = 2.0f / 0.9f;   // scaling / keep, folded into T
#pragma unroll
        for (int mi = 0; mi < 4; ++mi) {
            float lo, hi;
            unpack2f(acc2[mi][lane >> 1], lo, hi);
            float v = ((lane & 1) ? hi : lo) * CMUL;
            g_T2[(size_t)(m0 + wid * 4 + mi) * RANK_ + lane] = pack2f(v, v);
        }
    }
}

// ---------- k2: y = dropout( T @ B^T ), 64 rows/block, ILP-4 threefry ----------
__global__ void __launch_bounds__(256, 4) k2_by(const float* __restrict__ B,
                                                float* __restrict__ y) {
    __shared__ u64 B_s[RANK_][CBT / 2];  // 32 KB, col pairs (o even, o odd)
    __shared__ u64 T_s[RB][RANK_];       // 8 KB, (t,t) packed

    const int tid   = threadIdx.x;
    const int cb    = (blockIdx.x & 7) * CBT;           // col tile 0..7
    const int rbase = (blockIdx.x >> 3) * RB;           // row tile

    // stage B slice: thread t owns output cols {cb+2t, cb+2t+1}; their B rows
    // are contiguous 128 bytes -> 8 coalesced float4 loads, zero shuffles.
    {
        const float4* bp = reinterpret_cast<const float4*>(B + (size_t)(cb + 2 * tid) * RANK_);
        float4 r0 = bp[0], r1 = bp[1], r2 = bp[2], r3 = bp[3];   // row o = cb+2t
        float4 s0 = bp[4], s1 = bp[5], s2 = bp[6], s3 = bp[7];   // row o = cb+2t+1
        B_s[ 0][tid] = pack2f(r0.x, s0.x);
        B_s[ 1][tid] = pack2f(r0.y, s0.y);
        B_s[ 2][tid] = pack2f(r0.z, s0.z);
        B_s[ 3][tid] = pack2f(r0.w, s0.w);
        B_s[ 4][tid] = pack2f(r1.x, s1.x);
        B_s[ 5][tid] = pack2f(r1.y, s1.y);
        B_s[ 6][tid] = pack2f(r1.z, s1.z);
        B_s[ 7][tid] = pack2f(r1.w, s1.w);
        B_s[ 8][tid] = pack2f(r2.x, s2.x);
        B_s[ 9][tid] = pack2f(r2.y, s2.y);
        B_s[10][tid] = pack2f(r2.z, s2.z);
        B_s[11][tid] = pack2f(r2.w, s2.w);
        B_s[12][tid] = pack2f(r3.x, s3.x);
        B_s[13][tid] = pack2f(r3.y, s3.y);
        B_s[14][tid] = pack2f(r3.z, s3.z);
        B_s[15][tid] = pack2f(r3.w, s3.w);
    }
    // stage T rows: 64 rows x 16 = 1024 u64, 4 per thread (2 x LDG.128)
    {
        const ulonglong2* tp = reinterpret_cast<const ulonglong2*>(
            g_T2 + (size_t)rbase * RANK_);
        ulonglong2 t0 = tp[tid * 2];
        ulonglong2 t1 = tp[tid * 2 + 1];
        ulonglong2* ts = reinterpret_cast<ulonglong2*>(&T_s[0][0]);
        ts[tid * 2]     = t0;
        ts[tid * 2 + 1] = t1;
    }
    __syncthreads();

    // this thread's B column-pair, held across all rows
    u64 b[RANK_];
#pragma unroll
    for (int r = 0; r < RANK_; ++r) b[r] = B_s[r][tid];

#pragma unroll 1
    for (int q = 0; q < RB; q += 2) {
        u64 accA = 0ull, accB = 0ull;
#pragma unroll
        for (int rp = 0; rp < RANK_ / 2; ++rp) {
            ulonglong2 tA = *reinterpret_cast<const ulonglong2*>(&T_s[q][rp * 2]);
            ulonglong2 tB = *reinterpret_cast<const ulonglong2*>(&T_s[q + 1][rp * 2]);
            accA = ffma2(tA.x, b[rp * 2],     accA);
            accA = ffma2(tA.y, b[rp * 2 + 1], accA);
            accB = ffma2(tB.x, b[rp * 2],     accB);
            accB = ffma2(tB.y, b[rp * 2 + 1], accB);
        }
        float v0, v1, v2, v3;
        unpack2f(accA, v0, v1);
        unpack2f(accB, v2, v3);

        const int m = rbase + q;
        unsigned base_i = (unsigned)m * 4096u + (unsigned)(cb + tid * 2);
        uint4 bb = tf4(base_i, base_i + 1u, base_i + 4096u, base_i + 4097u);
        float o0 = (bb.x < TH_) ? v0 : 0.0f;
        float o1 = (bb.y < TH_) ? v1 : 0.0f;
        float o2 = (bb.z < TH_) ? v2 : 0.0f;
        float o3 = (bb.w < TH_) ? v3 : 0.0f;
        *reinterpret_cast<float2*>(&y[(size_t)m * 4096 + cb + tid * 2]) =
            make_float2(o0, o1);
        *reinterpret_cast<float2*>(&y[(size_t)(m + 1) * 4096 + cb + tid * 2]) =
            make_float2(o2, o3);
    }
}

extern "C" void kernel_launch(void* const* d_in, const int* in_sizes, int n_in,
                              void* d_out, int out_size) {
    const float* x = (const float*)d_in[0];
    const float* A = (const float*)d_in[1];
    const float* B = (const float*)d_in[2];
    float*       y = (float*)d_out;

    k1_xa<<<MROWS / BM1, 256>>>(x, A);
    k2_by<<<(MROWS / RB) * (OUT_F / CBT), 256>>>(B, y);
}